// round 4
// baseline (speedup 1.0000x reference)
#include <cuda_runtime.h>
#include <math.h>

// Problem constants (v0, v1: [8192, 256] fp32)
#define N_ROWS 8192
#define D      256
#define BM     128
#define BN     128
#define BK     32
#define APAD   4
#define NB     (N_ROWS / BM)          // 64 tile-rows
#define NTRI   (NB * (NB + 1) / 2)    // 2080 triangular tiles per view

// Scratch (no cudaMalloc allowed)
__device__ float  g_sq[2][N_ROWS];      // squared norms per row, per view
__device__ float  g_rowsum[2][N_ROWS];  // sum_j!=i exp(-d_ij), per view
__device__ double g_align;              // sum_i ||v0_i - v1_i||

// ---------------------------------------------------------------------------
// Kernel 0: zero scratch accumulators
// ---------------------------------------------------------------------------
__global__ void init_kernel() {
    int i = blockIdx.x * blockDim.x + threadIdx.x;
    if (i < 2 * N_ROWS) ((float*)g_rowsum)[i] = 0.0f;
    if (i == 0) g_align = 0.0;
}

// ---------------------------------------------------------------------------
// Kernel 1: per-row squared norms for both views + align term.
// One warp per (view,row). v0-warps also compute ||v0_r - v1_r||.
// ---------------------------------------------------------------------------
__global__ void sq_align_kernel(const float* __restrict__ v0,
                                const float* __restrict__ v1) {
    int w    = (blockIdx.x * blockDim.x + threadIdx.x) >> 5;  // global warp id
    int lane = threadIdx.x & 31;
    int view = w >> 13;            // 0..1
    int row  = w & (N_ROWS - 1);

    const float* z = view ? v1 : v0;
    const float4* p = (const float4*)(z + (size_t)row * D) + lane;  // 64 float4 per row
    float4 a0 = p[0];
    float4 a1 = p[32];
    float s = a0.x*a0.x + a0.y*a0.y + a0.z*a0.z + a0.w*a0.w
            + a1.x*a1.x + a1.y*a1.y + a1.z*a1.z + a1.w*a1.w;
    #pragma unroll
    for (int o = 16; o; o >>= 1) s += __shfl_xor_sync(0xffffffffu, s, o);
    if (lane == 0) g_sq[view][row] = s;

    if (view == 0) {
        const float4* q = (const float4*)(v1 + (size_t)row * D) + lane;
        float4 b0 = q[0];
        float4 b1 = q[32];
        float dx, ds = 0.0f;
        dx = a0.x - b0.x; ds += dx * dx;
        dx = a0.y - b0.y; ds += dx * dx;
        dx = a0.z - b0.z; ds += dx * dx;
        dx = a0.w - b0.w; ds += dx * dx;
        dx = a1.x - b1.x; ds += dx * dx;
        dx = a1.y - b1.y; ds += dx * dx;
        dx = a1.z - b1.z; ds += dx * dx;
        dx = a1.w - b1.w; ds += dx * dx;
        #pragma unroll
        for (int o = 16; o; o >>= 1) ds += __shfl_xor_sync(0xffffffffu, ds, o);
        if (lane == 0) atomicAdd(&g_align, (double)sqrtf(ds));
    }
}

// ---------------------------------------------------------------------------
// Kernel 2: fused triangular GEMM + exp epilogue.
// Each block computes one 128x128 tile (bi<=bj) of z z^T for one view,
// forms d = max(sqrt(max(sq_i+sq_j-2*dot,0)), eps), accumulates exp(-d)
// into rowsum[i] (and rowsum[j] for off-diagonal tiles, by symmetry).
// ---------------------------------------------------------------------------
__global__ void __launch_bounds__(256, 2)
pair_kernel(const float* __restrict__ v0, const float* __restrict__ v1) {
    const int view = blockIdx.y;
    const float* z = view ? v1 : v0;

    // Decode triangular tile index t -> (bi, bj), bi <= bj
    int t = blockIdx.x;
    float ff = 2.0f * NB + 1.0f;
    int bi = (int)((ff - sqrtf(ff * ff - 8.0f * (float)t)) * 0.5f);
    while ((bi + 1) * NB - ((bi + 1) * bi) / 2 <= t) bi++;
    while (bi * NB - (bi * (bi - 1)) / 2 > t) bi--;
    const int f_bi = bi * NB - (bi * (bi - 1)) / 2;
    const int bj = bi + (t - f_bi);
    const int I0 = bi * BM;
    const int J0 = bj * BN;
    const bool diag = (bi == bj);

    __shared__ float As[BK][BM + APAD];
    __shared__ float Bs[BK][BN + APAD];
    __shared__ float colbuf[BN];

    const int tid = threadIdx.x;        // 256 threads
    const int tx  = tid & 15;           // 16 column-groups
    const int ty  = tid >> 4;           // 16 row-groups

    const float* Ag = z + (size_t)I0 * D;
    const float* Bg = z + (size_t)J0 * D;

    float acc[8][8];
    #pragma unroll
    for (int i = 0; i < 8; i++)
        #pragma unroll
        for (int j = 0; j < 8; j++) acc[i][j] = 0.0f;

    for (int kt = 0; kt < D; kt += BK) {
        // Load 128x32 A and B tiles, transposed into smem [k][m]
        #pragma unroll
        for (int p = 0; p < 4; p++) {
            int e   = tid + p * 256;        // 0..1023 float4 slots
            int row = e >> 3;               // 8 float4 per row
            int c4  = (e & 7) * 4;
            float4 va = *(const float4*)(Ag + (size_t)row * D + kt + c4);
            As[c4 + 0][row] = va.x;
            As[c4 + 1][row] = va.y;
            As[c4 + 2][row] = va.z;
            As[c4 + 3][row] = va.w;
            float4 vb = *(const float4*)(Bg + (size_t)row * D + kt + c4);
            Bs[c4 + 0][row] = vb.x;
            Bs[c4 + 1][row] = vb.y;
            Bs[c4 + 2][row] = vb.z;
            Bs[c4 + 3][row] = vb.w;
        }
        __syncthreads();

        #pragma unroll 8
        for (int kk = 0; kk < BK; kk++) {
            float a[8], b[8];
            *(float4*)(a)     = *(const float4*)&As[kk][ty * 8];
            *(float4*)(a + 4) = *(const float4*)&As[kk][ty * 8 + 4];
            *(float4*)(b)     = *(const float4*)&Bs[kk][tx * 8];
            *(float4*)(b + 4) = *(const float4*)&Bs[kk][tx * 8 + 4];
            #pragma unroll
            for (int i = 0; i < 8; i++)
                #pragma unroll
                for (int j = 0; j < 8; j++)
                    acc[i][j] = fmaf(a[i], b[j], acc[i][j]);
        }
        __syncthreads();
    }

    // Epilogue: d2 -> d -> exp(-d), mask exact diagonal
    float sqi[8], sqj[8];
    #pragma unroll
    for (int i = 0; i < 8; i++) sqi[i] = g_sq[view][I0 + ty * 8 + i];
    #pragma unroll
    for (int j = 0; j < 8; j++) sqj[j] = g_sq[view][J0 + tx * 8 + j];

    float rowp[8], colp[8];
    #pragma unroll
    for (int i = 0; i < 8; i++) { rowp[i] = 0.0f; colp[i] = 0.0f; }

    #pragma unroll
    for (int i = 0; i < 8; i++) {
        int gi = I0 + ty * 8 + i;
        #pragma unroll
        for (int j = 0; j < 8; j++) {
            int gj = J0 + tx * 8 + j;
            float d2 = fmaxf(sqi[i] + sqj[j] - 2.0f * acc[i][j], 0.0f);
            float d  = fmaxf(sqrtf(d2), 1e-12f);
            float ex = (gi == gj) ? 0.0f : __expf(-d);
            rowp[i] += ex;
            colp[j] += ex;
        }
    }

    // Row sums: reduce across the 16 tx lanes (contiguous within warp half)
    #pragma unroll
    for (int i = 0; i < 8; i++) {
        float r = rowp[i];
        r += __shfl_xor_sync(0xffffffffu, r, 1);
        r += __shfl_xor_sync(0xffffffffu, r, 2);
        r += __shfl_xor_sync(0xffffffffu, r, 4);
        r += __shfl_xor_sync(0xffffffffu, r, 8);
        if (tx == 0) atomicAdd(&g_rowsum[view][I0 + ty * 8 + i], r);
    }

    // Column sums (only off-diagonal tiles; symmetric contribution to rows J0+*)
    if (!diag) {
        if (tid < BN) colbuf[tid] = 0.0f;
        __syncthreads();
        #pragma unroll
        for (int j = 0; j < 8; j++) {
            float c = colp[j] + __shfl_xor_sync(0xffffffffu, colp[j], 16);
            if ((tid & 16) == 0) atomicAdd(&colbuf[tx * 8 + j], c);
        }
        __syncthreads();
        if (tid < BN) atomicAdd(&g_rowsum[view][J0 + tid], colbuf[tid]);
    }
}

// ---------------------------------------------------------------------------
// Kernel 3: finalize — lme = log(rowsum) - log(n-1); out = align/n + mean lme
// ---------------------------------------------------------------------------
__global__ void finalize_kernel(float* __restrict__ out) {
    __shared__ double sbuf[256];
    int tid = threadIdx.x;
    double s = 0.0;
    for (int i = tid; i < 2 * N_ROWS; i += 256) {
        float rs = ((const float*)g_rowsum)[i];
        s += (double)logf(rs);
    }
    sbuf[tid] = s;
    __syncthreads();
    for (int o = 128; o; o >>= 1) {
        if (tid < o) sbuf[tid] += sbuf[tid + o];
        __syncthreads();
    }
    if (tid == 0) {
        double log_nm1  = log((double)(N_ROWS - 1));
        double entropy  = sbuf[0] / (2.0 * N_ROWS) - log_nm1;  // mean over both views
        double align    = g_align / (double)N_ROWS;
        out[0] = (float)(align + entropy);
    }
}

// ---------------------------------------------------------------------------
extern "C" void kernel_launch(void* const* d_in, const int* in_sizes, int n_in,
                              void* d_out, int out_size) {
    const float* v0 = (const float*)d_in[0];
    const float* v1 = (const float*)d_in[1];

    init_kernel<<<(2 * N_ROWS + 255) / 256, 256>>>();
    sq_align_kernel<<<(2 * N_ROWS) / 8, 256>>>(v0, v1);  // 8 warps/block, 1 warp per (view,row)
    dim3 grid(NTRI, 2);
    pair_kernel<<<grid, 256>>>(v0, v1);
    finalize_kernel<<<1, 256>>>((float*)d_out);
}

// round 10
// speedup vs baseline: 8.3691x; 8.3691x over previous
#include <cuda_runtime.h>
#include <cuda_bf16.h>
#include <cstdint>
#include <math.h>

// Problem constants (v0, v1: [8192, 256] fp32)
#define N_ROWS 8192
#define D      256
#define BM     128
#define BN     128
#define NB     (N_ROWS / BM)          // 64
#define NTRI   (NB * (NB + 1) / 2)    // 2080 triangular tiles per view
#define KC     64                     // K elems per smem stage
#define NSTAGE (D / KC)               // 4
#define STRIDE 72                     // bf16 elems per smem row (64 + 8 pad)
#define ROWB   144                    // bytes per smem row (conflict-free ldmatrix)
#define TILEB  (128 * ROWB)           // 18432 B per matrix tile
#define SM_SQJ 0
#define SM_AB  512
#define SMEM_BYTES (SM_AB + 2 * 2 * TILEB)  // 74240

// Scratch (no cudaMalloc allowed)
__device__ __nv_bfloat16 g_zb[2][N_ROWS * D];   // bf16 copies of v0/v1
__device__ float  g_sq[2][N_ROWS];
__device__ float  g_rowsum[2][N_ROWS];
__device__ double g_align;
__device__ double g_logsum;

// ---------------------------------------------------------------------------
// PTX helpers (baseline sm_80+ features only — ptxas here targets plain sm_103)
// ---------------------------------------------------------------------------
__device__ __forceinline__ uint32_t smem_u32(const void* p) {
    uint32_t a;
    asm("{ .reg .u64 t; cvta.to.shared.u64 t, %1; cvt.u32.u64 %0, t; }" : "=r"(a) : "l"(p));
    return a;
}

__device__ __forceinline__ void ldm4(uint32_t* r, uint32_t addr) {
    asm volatile("ldmatrix.sync.aligned.m8n8.x4.shared.b16 {%0,%1,%2,%3}, [%4];"
                 : "=r"(r[0]), "=r"(r[1]), "=r"(r[2]), "=r"(r[3]) : "r"(addr));
}

__device__ __forceinline__ void mma_bf16(float* d, const uint32_t* a, const uint32_t* b) {
    asm volatile(
        "mma.sync.aligned.m16n8k16.row.col.f32.bf16.bf16.f32 "
        "{%0,%1,%2,%3}, {%4,%5,%6,%7}, {%8,%9}, {%0,%1,%2,%3};"
        : "+f"(d[0]), "+f"(d[1]), "+f"(d[2]), "+f"(d[3])
        : "r"(a[0]), "r"(a[1]), "r"(a[2]), "r"(a[3]), "r"(b[0]), "r"(b[1]));
}

#define CP_ASYNC16(saddr, gaddr) \
    asm volatile("cp.async.cg.shared.global [%0], [%1], 16;" :: "r"(saddr), "l"(gaddr))
#define CP_COMMIT() asm volatile("cp.async.commit_group;")

// ---------------------------------------------------------------------------
// Kernel 0: zero accumulators
// ---------------------------------------------------------------------------
__global__ void init_kernel() {
    int i = blockIdx.x * blockDim.x + threadIdx.x;
    if (i < 2 * N_ROWS) ((float*)g_rowsum)[i] = 0.0f;
    if (i == 0) { g_align = 0.0; g_logsum = 0.0; }
}

// ---------------------------------------------------------------------------
// Kernel 1: bf16 convert + per-row squared norms + align term.
// One warp per (view,row).
// ---------------------------------------------------------------------------
__global__ void prep_kernel(const float* __restrict__ v0,
                            const float* __restrict__ v1) {
    int w    = (blockIdx.x * blockDim.x + threadIdx.x) >> 5;
    int lane = threadIdx.x & 31;
    int view = w >> 13;
    int row  = w & (N_ROWS - 1);

    const float* z = view ? v1 : v0;
    const float4* p = (const float4*)(z + (size_t)row * D) + lane;
    float4 a0 = p[0], a1 = p[32];

    // bf16 copy
    __nv_bfloat162* q = (__nv_bfloat162*)(g_zb[view] + (size_t)row * D);
    q[lane * 2 + 0]      = __floats2bfloat162_rn(a0.x, a0.y);
    q[lane * 2 + 1]      = __floats2bfloat162_rn(a0.z, a0.w);
    q[64 + lane * 2 + 0] = __floats2bfloat162_rn(a1.x, a1.y);
    q[64 + lane * 2 + 1] = __floats2bfloat162_rn(a1.z, a1.w);

    // squared norm (fp32)
    float s = a0.x*a0.x + a0.y*a0.y + a0.z*a0.z + a0.w*a0.w
            + a1.x*a1.x + a1.y*a1.y + a1.z*a1.z + a1.w*a1.w;
    #pragma unroll
    for (int o = 16; o; o >>= 1) s += __shfl_xor_sync(0xffffffffu, s, o);
    if (lane == 0) g_sq[view][row] = s;

    // align term (view 0 warps only)
    if (view == 0) {
        const float4* qq = (const float4*)(v1 + (size_t)row * D) + lane;
        float4 b0 = qq[0], b1 = qq[32];
        float dx, ds = 0.0f;
        dx = a0.x - b0.x; ds += dx * dx;  dx = a0.y - b0.y; ds += dx * dx;
        dx = a0.z - b0.z; ds += dx * dx;  dx = a0.w - b0.w; ds += dx * dx;
        dx = a1.x - b1.x; ds += dx * dx;  dx = a1.y - b1.y; ds += dx * dx;
        dx = a1.z - b1.z; ds += dx * dx;  dx = a1.w - b1.w; ds += dx * dx;
        #pragma unroll
        for (int o = 16; o; o >>= 1) ds += __shfl_xor_sync(0xffffffffu, ds, o);
        if (lane == 0) atomicAdd(&g_align, (double)sqrtf(ds));
    }
}

// ---------------------------------------------------------------------------
// Kernel 2: triangular tiled bf16 mma.sync GEMM + exp epilogue.
// One 128x128 tile (bi<=bj) per block per view. 8 warps in 4(m) x 2(n),
// warp tile 32x64 via m16n8k16 fragments. Row sums always; column sums
// (symmetric contribution) for off-diagonal tiles.
// ---------------------------------------------------------------------------
__global__ void __launch_bounds__(256, 2)
pair_mma_kernel() {
    extern __shared__ char smem[];
    const int view = blockIdx.y;

    // Decode triangular tile index t -> (bi, bj), bi <= bj
    int t = blockIdx.x;
    float ff = 2.0f * NB + 1.0f;
    int bi = (int)((ff - sqrtf(ff * ff - 8.0f * (float)t)) * 0.5f);
    while ((bi + 1) * NB - ((bi + 1) * bi) / 2 <= t) bi++;
    while (bi * NB - (bi * (bi - 1)) / 2 > t) bi--;
    const int bj = bi + (t - (bi * NB - (bi * (bi - 1)) / 2));
    const int I0 = bi * BM;
    const int J0 = bj * BN;
    const bool diag = (bi == bj);

    const int tid  = threadIdx.x;
    const int lane = tid & 31;
    const int wrp  = tid >> 5;
    const int wm   = wrp & 3;     // m-position (0..3) * 32
    const int wn   = wrp >> 2;    // n-position (0..1) * 64

    const __nv_bfloat16* zb = g_zb[view];
    float* sqj_s = (float*)(smem + SM_SQJ);
    if (tid < 128) sqj_s[tid] = g_sq[view][J0 + tid];

    const uint32_t sb = smem_u32(smem) + SM_AB;

    // --- async stage loader: 128 rows x 64 bf16 for A and B ---
    auto load_stage = [&](int s) {
        uint32_t buf = sb + (uint32_t)(s & 1) * (2 * TILEB);
        const __nv_bfloat16* ga = zb + (size_t)I0 * D + s * KC;
        const __nv_bfloat16* gb = zb + (size_t)J0 * D + s * KC;
        #pragma unroll
        for (int p = 0; p < 4; p++) {
            int idx = tid + p * 256;          // 0..1023 16B segments
            int row = idx >> 3, c = idx & 7;
            uint32_t so = (uint32_t)(row * ROWB + c * 16);
            CP_ASYNC16(buf + so,         ga + (size_t)row * D + c * 8);
            CP_ASYNC16(buf + TILEB + so, gb + (size_t)row * D + c * 8);
        }
        CP_COMMIT();
    };

    float acc[2][8][4];
    #pragma unroll
    for (int f = 0; f < 2; f++)
        #pragma unroll
        for (int nf = 0; nf < 8; nf++)
            #pragma unroll
            for (int r = 0; r < 4; r++) acc[f][nf][r] = 0.0f;

    // ldmatrix per-lane offsets
    const int a_m = wm * 32 + ((lane >> 3) & 1) * 8 + (lane & 7);
    const int a_k = (lane >> 4) * 8;
    const int b_n = wn * 64 + (lane >> 4) * 8 + (lane & 7);
    const int b_k = ((lane >> 3) & 1) * 8;

    load_stage(0);
    for (int s = 0; s < NSTAGE; s++) {
        if (s < NSTAGE - 1) {
            load_stage(s + 1);
            asm volatile("cp.async.wait_group 1;");
        } else {
            asm volatile("cp.async.wait_group 0;");
        }
        __syncthreads();

        const uint32_t Ab = sb + (uint32_t)(s & 1) * (2 * TILEB);
        const uint32_t Bb = Ab + TILEB;
        #pragma unroll
        for (int ks = 0; ks < 4; ks++) {              // 4 x k16 per stage
            uint32_t a[2][4], b[4][4];
            #pragma unroll
            for (int f = 0; f < 2; f++)
                ldm4(a[f], Ab + (uint32_t)((a_m + f * 16) * ROWB + (a_k + ks * 16) * 2));
            #pragma unroll
            for (int p2 = 0; p2 < 4; p2++)
                ldm4(b[p2], Bb + (uint32_t)((b_n + p2 * 16) * ROWB + (b_k + ks * 16) * 2));
            #pragma unroll
            for (int f = 0; f < 2; f++)
                #pragma unroll
                for (int p2 = 0; p2 < 4; p2++) {
                    mma_bf16(acc[f][p2 * 2],     a[f], &b[p2][0]);
                    mma_bf16(acc[f][p2 * 2 + 1], a[f], &b[p2][2]);
                }
        }
        __syncthreads();
    }

    // --- Epilogue ---
    const int gi0 = I0 + wm * 32 + (lane >> 2);   // +f*16 +h*8 for fragments
    float sqi[2][2];
    #pragma unroll
    for (int f = 0; f < 2; f++) {
        sqi[f][0] = g_sq[view][gi0 + f * 16];
        sqi[f][1] = g_sq[view][gi0 + f * 16 + 8];
    }

    float rowp[2][2] = {{0.0f, 0.0f}, {0.0f, 0.0f}};
    float colp[16];
    #pragma unroll
    for (int k = 0; k < 16; k++) colp[k] = 0.0f;

    #pragma unroll
    for (int f = 0; f < 2; f++)
        #pragma unroll
        for (int nf = 0; nf < 8; nf++) {
            const int cl  = wn * 64 + nf * 8 + (lane & 3) * 2;
            const float sj0 = sqj_s[cl], sj1 = sqj_s[cl + 1];
            const int gj0 = J0 + cl;
            #pragma unroll
            for (int r = 0; r < 4; r++) {
                const int half = r >> 1, par = r & 1;
                const int gi = gi0 + f * 16 + half * 8;
                const int gj = gj0 + par;
                const float sj = par ? sj1 : sj0;
                float d2 = fmaxf(fmaf(-2.0f, acc[f][nf][r], sqi[f][half] + sj), 1e-24f);
                float dd = d2 * rsqrtf(d2);             // sqrt, 1 MUFU
                float ex = (gi == gj) ? 0.0f : __expf(-dd);
                rowp[f][half]      += ex;
                colp[nf * 2 + par] += ex;
            }
        }

    // Row sums: reduce across the 4 lanes sharing each row (lane&3)
    #pragma unroll
    for (int f = 0; f < 2; f++)
        #pragma unroll
        for (int h = 0; h < 2; h++) {
            float v = rowp[f][h];
            v += __shfl_xor_sync(0xffffffffu, v, 1);
            v += __shfl_xor_sync(0xffffffffu, v, 2);
            if ((lane & 3) == 0)
                atomicAdd(&g_rowsum[view][gi0 + f * 16 + h * 8], v);
        }

    // Column sums (off-diagonal only): reduce across lanes sharing each column
    if (!diag) {
        #pragma unroll
        for (int nf = 0; nf < 8; nf++)
            #pragma unroll
            for (int par = 0; par < 2; par++) {
                float v = colp[nf * 2 + par];
                v += __shfl_xor_sync(0xffffffffu, v, 4);
                v += __shfl_xor_sync(0xffffffffu, v, 8);
                v += __shfl_xor_sync(0xffffffffu, v, 16);
                if (lane < 4)
                    atomicAdd(&g_rowsum[view][J0 + wn * 64 + nf * 8 + lane * 2 + par], v);
            }
    }
}

// ---------------------------------------------------------------------------
// Kernel 3a: parallel log-reduction of rowsums
// ---------------------------------------------------------------------------
__global__ void entropy_reduce_kernel() {
    __shared__ double sb[256];
    int tid = threadIdx.x;
    int i = blockIdx.x * 256 + tid;
    float rs = ((const float*)g_rowsum)[i];
    double s = (double)logf(rs);
    sb[tid] = s;
    __syncthreads();
    for (int o = 128; o; o >>= 1) {
        if (tid < o) sb[tid] += sb[tid + o];
        __syncthreads();
    }
    if (tid == 0) atomicAdd(&g_logsum, sb[0]);
}

// Kernel 3b: scalar finalize
__global__ void finalize_kernel(float* __restrict__ out) {
    double log_nm1 = log((double)(N_ROWS - 1));
    double entropy = g_logsum / (2.0 * N_ROWS) - log_nm1;
    double align   = g_align / (double)N_ROWS;
    out[0] = (float)(align + entropy);
}

// ---------------------------------------------------------------------------
extern "C" void kernel_launch(void* const* d_in, const int* in_sizes, int n_in,
                              void* d_out, int out_size) {
    const float* v0 = (const float*)d_in[0];
    const float* v1 = (const float*)d_in[1];

    cudaFuncSetAttribute(pair_mma_kernel,
                         cudaFuncAttributeMaxDynamicSharedMemorySize, SMEM_BYTES);

    init_kernel<<<(2 * N_ROWS + 255) / 256, 256>>>();
    prep_kernel<<<(2 * N_ROWS) / 8, 256>>>(v0, v1);
    dim3 grid(NTRI, 2);
    pair_mma_kernel<<<grid, 256, SMEM_BYTES>>>();
    entropy_reduce_kernel<<<(2 * N_ROWS) / 256, 256>>>();
    finalize_kernel<<<1, 1>>>((float*)d_out);
}

// round 12
// speedup vs baseline: 8.5746x; 1.0246x over previous
#include <cuda_runtime.h>
#include <cuda_bf16.h>
#include <cstdint>
#include <math.h>

// Problem constants (v0, v1: [8192, 256] fp32)
#define N_ROWS 8192
#define D      256
#define BM     128
#define BN     128
#define NB     (N_ROWS / BM)          // 64
#define NTRI   (NB * (NB + 1) / 2)    // 2080 triangular tiles per view
#define NTILES (2 * NTRI)             // 4160
#define NBLK   296                    // 2 CTAs/SM x 148 SMs, one wave
#define KC     64                     // K elems per B smem stage
#define NSTAGE (D / KC)               // 4
#define ROWA   528                    // A smem row bytes (512 + 16 pad)
#define ROWB_  144                    // B smem row bytes (128 + 16 pad)
#define A_BYTES (128 * ROWA)          // 67584
#define BSTG    (128 * ROWB_)         // 18432
#define SM_B    A_BYTES
#define SMEM_BYTES (A_BYTES + 2 * BSTG)   // 104448 -> 2 CTAs/SM

// Scratch (no cudaMalloc allowed)
__device__ __nv_bfloat16 g_zb[2][N_ROWS * D];   // bf16 copies of v0/v1
__device__ float g_sq[2][N_ROWS];               // squared norms (fp32)
__device__ float g_rowsum[2][N_ROWS];           // sum_j!=i exp(-d_ij)
__device__ float g_alignrow[N_ROWS];            // per-row ||v0_i - v1_i||

// ---------------------------------------------------------------------------
// PTX helpers (baseline sm_80+ features only: ptxas targets plain sm_103)
// ---------------------------------------------------------------------------
__device__ __forceinline__ uint32_t smem_u32(const void* p) {
    uint32_t a;
    asm("{ .reg .u64 t; cvta.to.shared.u64 t, %1; cvt.u32.u64 %0, t; }" : "=r"(a) : "l"(p));
    return a;
}
__device__ __forceinline__ void ldm4(uint32_t* r, uint32_t addr) {
    asm volatile("ldmatrix.sync.aligned.m8n8.x4.shared.b16 {%0,%1,%2,%3}, [%4];"
                 : "=r"(r[0]), "=r"(r[1]), "=r"(r[2]), "=r"(r[3]) : "r"(addr));
}
__device__ __forceinline__ void mma_bf16(float* d, const uint32_t* a, const uint32_t* b) {
    asm volatile(
        "mma.sync.aligned.m16n8k16.row.col.f32.bf16.bf16.f32 "
        "{%0,%1,%2,%3}, {%4,%5,%6,%7}, {%8,%9}, {%0,%1,%2,%3};"
        : "+f"(d[0]), "+f"(d[1]), "+f"(d[2]), "+f"(d[3])
        : "r"(a[0]), "r"(a[1]), "r"(a[2]), "r"(a[3]), "r"(b[0]), "r"(b[1]));
}
#define CP_ASYNC16(saddr, gaddr) \
    asm volatile("cp.async.cg.shared.global [%0], [%1], 16;" :: "r"(saddr), "l"(gaddr))
#define CP_COMMIT() asm volatile("cp.async.commit_group;")

__device__ __forceinline__ void decode_tile(int t, int& bi, int& bj) {
    float ff = 2.0f * NB + 1.0f;
    int b = (int)((ff - sqrtf(ff * ff - 8.0f * (float)t)) * 0.5f);
    while ((b + 1) * NB - ((b + 1) * b) / 2 <= t) b++;
    while (b * NB - (b * (b - 1)) / 2 > t) b--;
    bi = b;
    bj = b + (t - (b * NB - (b * (b - 1)) / 2));
}

// ---------------------------------------------------------------------------
// Kernel 1: bf16 convert + squared norms + per-row align + zero rowsum.
// One warp per (view,row). Replaces the old init kernel too.
// ---------------------------------------------------------------------------
__global__ void prep_kernel(const float* __restrict__ v0,
                            const float* __restrict__ v1) {
    int w    = (blockIdx.x * blockDim.x + threadIdx.x) >> 5;
    int lane = threadIdx.x & 31;
    int view = w >> 13;
    int row  = w & (N_ROWS - 1);

    const float* z = view ? v1 : v0;
    const float4* p = (const float4*)(z + (size_t)row * D) + lane;
    float4 a0 = p[0], a1 = p[32];

    __nv_bfloat162* q = (__nv_bfloat162*)(g_zb[view] + (size_t)row * D);
    q[lane * 2 + 0]      = __floats2bfloat162_rn(a0.x, a0.y);
    q[lane * 2 + 1]      = __floats2bfloat162_rn(a0.z, a0.w);
    q[64 + lane * 2 + 0] = __floats2bfloat162_rn(a1.x, a1.y);
    q[64 + lane * 2 + 1] = __floats2bfloat162_rn(a1.z, a1.w);

    float s = a0.x*a0.x + a0.y*a0.y + a0.z*a0.z + a0.w*a0.w
            + a1.x*a1.x + a1.y*a1.y + a1.z*a1.z + a1.w*a1.w;
    #pragma unroll
    for (int o = 16; o; o >>= 1) s += __shfl_xor_sync(0xffffffffu, s, o);
    if (lane == 0) { g_sq[view][row] = s; g_rowsum[view][row] = 0.0f; }

    if (view == 0) {
        const float4* qq = (const float4*)(v1 + (size_t)row * D) + lane;
        float4 b0 = qq[0], b1 = qq[32];
        float dx, ds = 0.0f;
        dx = a0.x - b0.x; ds += dx * dx;  dx = a0.y - b0.y; ds += dx * dx;
        dx = a0.z - b0.z; ds += dx * dx;  dx = a0.w - b0.w; ds += dx * dx;
        dx = a1.x - b1.x; ds += dx * dx;  dx = a1.y - b1.y; ds += dx * dx;
        dx = a1.z - b1.z; ds += dx * dx;  dx = a1.w - b1.w; ds += dx * dx;
        #pragma unroll
        for (int o = 16; o; o >>= 1) ds += __shfl_xor_sync(0xffffffffu, ds, o);
        if (lane == 0) g_alignrow[row] = sqrtf(ds);
    }
}

// ---------------------------------------------------------------------------
// Kernel 2: persistent triangular bf16 mma.sync sweep.
// 296 blocks; each owns ~14 consecutive tiles of the (view, bi<=bj) list.
// A panel (128x256) resident in smem per (view,bi); B streamed in 4 double-
// buffered K-stages with cross-tile preload; per-thread row sums persist
// across the panel (atomics once per panel-segment).
// ---------------------------------------------------------------------------
__global__ void __launch_bounds__(256, 2)
pair_persist_kernel() {
    extern __shared__ char smem[];
    const uint32_t sA = smem_u32(smem);
    const uint32_t sB = sA + SM_B;

    const int tid  = threadIdx.x;
    const int lane = tid & 31;
    const int wrp  = tid >> 5;
    const int wm   = wrp & 3;     // m-position (0..3) * 32
    const int wn   = wrp >> 2;    // n-position (0..1) * 64

    // Tile range for this block: 4160 = 296*14 + 16
    const int b  = blockIdx.x;
    const int t0 = 14 * b + min(b, 16);
    const int t1 = t0 + 14 + (b < 16 ? 1 : 0);

    // ldmatrix per-lane geometry
    const int a_m = wm * 32 + ((lane >> 3) & 1) * 8 + (lane & 7);
    const uint32_t a_off0 = (uint32_t)(a_m * ROWA)        + (uint32_t)((lane >> 4) * 16);
    const uint32_t a_off1 = (uint32_t)((a_m + 16) * ROWA) + (uint32_t)((lane >> 4) * 16);
    const int b_n = wn * 64 + (lane >> 4) * 8 + (lane & 7);
    const uint32_t b_off = (uint32_t)(b_n * ROWB_) + (uint32_t)(((lane >> 3) & 1) * 16);

    const int ep_row = lane >> 2;                 // epilogue row within warp m-tile
    const int ep_cl  = wn * 64 + (lane & 3) * 2;  // epilogue col base within tile

    int cur_view = -1, cur_bi = -1, cur_I0 = 0;
    const __nv_bfloat16* zb = g_zb[0];
    float rowp[2][2];
    float sqi[2][2];
    bool have_preload = false;

    auto loadB = [&](int J0, int s, int buf) {
        uint32_t bbase = sB + (uint32_t)buf * BSTG;
        const __nv_bfloat16* gb = zb + (size_t)J0 * D + s * KC;
        #pragma unroll
        for (int p = 0; p < 4; p++) {
            int idx = tid + p * 256;
            int row = idx >> 3, c = idx & 7;
            CP_ASYNC16(bbase + (uint32_t)(row * ROWB_ + c * 16),
                       gb + (size_t)row * D + c * 8);
        }
        CP_COMMIT();
    };

    auto flush_rows = [&]() {
        #pragma unroll
        for (int f = 0; f < 2; f++)
            #pragma unroll
            for (int h = 0; h < 2; h++) {
                float v = rowp[f][h];
                v += __shfl_xor_sync(0xffffffffu, v, 1);
                v += __shfl_xor_sync(0xffffffffu, v, 2);
                if ((lane & 3) == 0)
                    atomicAdd(&g_rowsum[cur_view][cur_I0 + wm * 32 + ep_row + f * 16 + h * 8], v);
            }
    };

    for (int g = t0; g < t1; g++) {
        const int view = g / NTRI;
        int bi, bj;
        decode_tile(g - view * NTRI, bi, bj);
        const int I0 = bi * BM, J0 = bj * BN;
        const bool diag = (bi == bj);

        // Panel switch: flush rows, load A panel, reset state
        if (view != cur_view || bi != cur_bi) {
            if (cur_bi >= 0) flush_rows();
            cur_view = view; cur_bi = bi; cur_I0 = I0;
            zb = g_zb[view];
            const __nv_bfloat16* ga = zb + (size_t)I0 * D;
            #pragma unroll
            for (int p = 0; p < 16; p++) {
                int idx = tid + p * 256;
                int row = idx >> 5, c = idx & 31;
                CP_ASYNC16(sA + (uint32_t)(row * ROWA + c * 16),
                           ga + (size_t)row * D + c * 8);
            }
            __syncthreads();        // all prior reads of old A done before... (tail sync of prev tile also covers)
            loadB(J0, 0, 0);        // A ops join this commit group
            have_preload = true;
            #pragma unroll
            for (int f = 0; f < 2; f++)
                #pragma unroll
                for (int h = 0; h < 2; h++) {
                    rowp[f][h] = 0.0f;
                    sqi[f][h] = g_sq[view][I0 + wm * 32 + ep_row + f * 16 + h * 8];
                }
        } else if (!have_preload) {
            loadB(J0, 0, 0);
        }

        // Peek next tile for cross-tile preload
        bool next_same = false;
        int nJ0 = 0;
        if (g + 1 < t1) {
            int nview = (g + 1) / NTRI, nbi, nbj;
            decode_tile((g + 1) - nview * NTRI, nbi, nbj);
            if (nview == view && nbi == bi) { next_same = true; nJ0 = nbj * BN; }
        }

        float acc[2][8][4];
        #pragma unroll
        for (int f = 0; f < 2; f++)
            #pragma unroll
            for (int nf = 0; nf < 8; nf++)
                #pragma unroll
                for (int r = 0; r < 4; r++) acc[f][nf][r] = 0.0f;

        #pragma unroll
        for (int s = 0; s < NSTAGE; s++) {
            if (s < NSTAGE - 1)       loadB(J0, s + 1, (s + 1) & 1);
            else if (next_same)       loadB(nJ0, 0, 0);

            if (s < NSTAGE - 1 || next_same)
                asm volatile("cp.async.wait_group 1;");
            else
                asm volatile("cp.async.wait_group 0;");
            __syncthreads();

            const uint32_t Bb = sB + (uint32_t)(s & 1) * BSTG;
            const uint32_t Acol = (uint32_t)(s * 128);
            #pragma unroll
            for (int ks = 0; ks < 4; ks++) {
                uint32_t a[2][4], bb[4][4];
                ldm4(a[0], sA + a_off0 + Acol + ks * 32);
                ldm4(a[1], sA + a_off1 + Acol + ks * 32);
                #pragma unroll
                for (int p2 = 0; p2 < 4; p2++)
                    ldm4(bb[p2], Bb + b_off + (uint32_t)(p2 * 16 * ROWB_) + ks * 32);
                #pragma unroll
                for (int f = 0; f < 2; f++)
                    #pragma unroll
                    for (int p2 = 0; p2 < 4; p2++) {
                        mma_bf16(acc[f][p2 * 2],     a[f], &bb[p2][0]);
                        mma_bf16(acc[f][p2 * 2 + 1], a[f], &bb[p2][2]);
                    }
            }
            __syncthreads();
        }
        have_preload = next_same;

        // --- Epilogue (overlaps next tile's in-flight cp.async) ---
        const int gi0 = I0 + wm * 32 + ep_row;
        float colp[16];
        #pragma unroll
        for (int k = 0; k < 16; k++) colp[k] = 0.0f;

        #pragma unroll
        for (int f = 0; f < 2; f++)
            #pragma unroll
            for (int nf = 0; nf < 8; nf++) {
                const int cl  = ep_cl + nf * 8;
                const float2 sj2 = *(const float2*)&g_sq[view][J0 + cl];
                const int gj0 = J0 + cl;
                #pragma unroll
                for (int r = 0; r < 4; r++) {
                    const int half = r >> 1, par = r & 1;
                    const int gi = gi0 + f * 16 + half * 8;
                    const int gj = gj0 + par;
                    const float sj = par ? sj2.y : sj2.x;
                    float d2 = fmaxf(fmaf(-2.0f, acc[f][nf][r], sqi[f][half] + sj), 1e-24f);
                    float dd = d2 * rsqrtf(d2);          // sqrt, 1 MUFU
                    float ex = (gi == gj) ? 0.0f : __expf(-dd);
                    rowp[f][half]      += ex;
                    colp[nf * 2 + par] += ex;
                }
            }

        // Column sums (symmetric contribution), off-diagonal tiles only
        if (!diag) {
            #pragma unroll
            for (int nf = 0; nf < 8; nf++)
                #pragma unroll
                for (int par = 0; par < 2; par++) {
                    float v = colp[nf * 2 + par];
                    v += __shfl_xor_sync(0xffffffffu, v, 4);
                    v += __shfl_xor_sync(0xffffffffu, v, 8);
                    v += __shfl_xor_sync(0xffffffffu, v, 16);
                    if (lane < 4)
                        atomicAdd(&g_rowsum[view][J0 + wn * 64 + nf * 8 + lane * 2 + par], v);
                }
        }
    }
    if (cur_bi >= 0) flush_rows();
}

// ---------------------------------------------------------------------------
// Kernel 3: single-block finalize — no global accumulators, no atomics.
// out = mean(alignrow) + mean(log(rowsum))/1 - log(n-1)   (mean over 2 views)
// ---------------------------------------------------------------------------
__global__ void final_kernel(float* __restrict__ out) {
    __shared__ double sb[1024];
    const int tid = threadIdx.x;
    double s = 0.0;
    for (int i = tid; i < 2 * N_ROWS; i += 1024)
        s += (double)__logf(((const float*)g_rowsum)[i]) * (1.0 / (2.0 * N_ROWS));
    for (int i = tid; i < N_ROWS; i += 1024)
        s += (double)g_alignrow[i] * (1.0 / N_ROWS);
    sb[tid] = s;
    __syncthreads();
    for (int o = 512; o; o >>= 1) {
        if (tid < o) sb[tid] += sb[tid + o];
        __syncthreads();
    }
    if (tid == 0)
        out[0] = (float)(sb[0] - log((double)(N_ROWS - 1)));
}

// ---------------------------------------------------------------------------
extern "C" void kernel_launch(void* const* d_in, const int* in_sizes, int n_in,
                              void* d_out, int out_size) {
    const float* v0 = (const float*)d_in[0];
    const float* v1 = (const float*)d_in[1];

    cudaFuncSetAttribute(pair_persist_kernel,
                         cudaFuncAttributeMaxDynamicSharedMemorySize, SMEM_BYTES);

    prep_kernel<<<(2 * N_ROWS) / 8, 256>>>(v0, v1);
    pair_persist_kernel<<<NBLK, 256, SMEM_BYTES>>>();
    final_kernel<<<1, 1024>>>((float*)d_out);
}